// round 4
// baseline (speedup 1.0000x reference)
#include <cuda_runtime.h>

// realignment_layer: inputs (metadata order)
//   d_in[0] pcd_mis      float32 (32, 262144, 3)
//   d_in[1] T_mis        float32 (32, 4, 4)
//   d_in[2] delta_q_pred float32 (32, 4)
//   d_in[3] delta_t_pred float32 (32, 3)
// output: concat(batch_T_pred (32,4,4) -> 512 floats, pcd_new (32,262144,3))

static constexpr int B = 32;
static constexpr int NPTS = 262144;
static constexpr int FLOATS_PER_BATCH = NPTS * 3;          // 786432
static constexpr int THREADS = 256;
static constexpr int F4_PER_THREAD = 6;                    // 8 points = 24 floats
static constexpr int BLOCKS_PER_BATCH =
    FLOATS_PER_BATCH / (THREADS * F4_PER_THREAD * 4);      // 128
static constexpr int TOTAL_BLOCKS = B * BLOCKS_PER_BATCH;  // 4096

// Closed-form inverse of [[R(q), t],[0,0,0,1]] with q normalized:
// invR = R^T, inv_t = -R^T t.  m is row-major 3x3 of invR.
__device__ __forceinline__ void compute_inv(const float* __restrict__ q,
                                            const float* __restrict__ t,
                                            float m[9], float it[3]) {
    float w = q[0], x = q[1], y = q[2], z = q[3];
    float s = rsqrtf(w * w + x * x + y * y + z * z);
    w *= s; x *= s; y *= s; z *= s;
    float r00 = 1.f - 2.f * (y * y + z * z);
    float r01 = 2.f * (x * y - z * w);
    float r02 = 2.f * (x * z + y * w);
    float r10 = 2.f * (x * y + z * w);
    float r11 = 1.f - 2.f * (x * x + z * z);
    float r12 = 2.f * (y * z - x * w);
    float r20 = 2.f * (x * z - y * w);
    float r21 = 2.f * (y * z + x * w);
    float r22 = 1.f - 2.f * (x * x + y * y);
    // invR = R^T
    m[0] = r00; m[1] = r10; m[2] = r20;
    m[3] = r01; m[4] = r11; m[5] = r21;
    m[6] = r02; m[7] = r12; m[8] = r22;
    float tx = t[0], ty = t[1], tz = t[2];
    it[0] = -(m[0] * tx + m[1] * ty + m[2] * tz);
    it[1] = -(m[3] * tx + m[4] * ty + m[5] * tz);
    it[2] = -(m[6] * tx + m[7] * ty + m[8] * tz);
}

// Fused kernel: streaming point transform (8 pts/thread, float4 vectorized)
// plus batch_T_pred computed by threads 0-15 of the first 32 blocks.
__global__ __launch_bounds__(THREADS)
void pcd_kernel(const float4* __restrict__ in,
                const float* __restrict__ T_mis,
                const float* __restrict__ q,
                const float* __restrict__ t,
                float4* __restrict__ out,      // pcd_new region
                float* __restrict__ tout) {    // batch_T_pred region (512 floats)
    __shared__ float sm[12];
    int b = blockIdx.x >> 7;  // 128 blocks per batch

    if (threadIdx.x == 0) {
        float m[9], it[3];
        compute_inv(q + b * 4, t + b * 3, m, it);
        #pragma unroll
        for (int i = 0; i < 9; i++) sm[i] = m[i];
        sm[9] = it[0]; sm[10] = it[1]; sm[11] = it[2];
    }
    __syncthreads();

    const float m0 = sm[0], m1 = sm[1], m2 = sm[2];
    const float m3 = sm[3], m4 = sm[4], m5 = sm[5];
    const float m6 = sm[6], m7 = sm[7], m8 = sm[8];
    const float t0 = sm[9], t1 = sm[10], t2 = sm[11];

    size_t idx4 = ((size_t)blockIdx.x * THREADS + threadIdx.x) * F4_PER_THREAD;

    float4 v[F4_PER_THREAD];
    #pragma unroll
    for (int i = 0; i < F4_PER_THREAD; i++)
        v[i] = __ldcs(&in[idx4 + i]);

    // 8 points packed across 6 float4s; transform in place back into float4s.
    const float* p = (const float*)v;
    float o[24];
    #pragma unroll
    for (int i = 0; i < 8; i++) {
        float px = p[i * 3 + 0], py = p[i * 3 + 1], pz = p[i * 3 + 2];
        o[i * 3 + 0] = m0 * px + m1 * py + m2 * pz + t0;
        o[i * 3 + 1] = m3 * px + m4 * py + m5 * pz + t1;
        o[i * 3 + 2] = m6 * px + m7 * py + m8 * pz + t2;
    }
    const float4* ov = (const float4*)o;
    #pragma unroll
    for (int i = 0; i < F4_PER_THREAD; i++)
        __stcs(&out[idx4 + i], ov[i]);

    // Fused batch_T_pred: blocks 0..31, threads 0..15.
    if (blockIdx.x < B && threadIdx.x < 16) {
        int bb = blockIdx.x;
        int i = threadIdx.x >> 2;   // row
        int k = threadIdx.x & 3;    // col
        float m[9], it[3];
        compute_inv(q + bb * 4, t + bb * 3, m, it);
        float row0, row1, row2, row3;
        if (i < 3) {
            row0 = m[i * 3 + 0]; row1 = m[i * 3 + 1];
            row2 = m[i * 3 + 2]; row3 = it[i];
        } else {
            row0 = 0.f; row1 = 0.f; row2 = 0.f; row3 = 1.f;
        }
        const float* Tb = T_mis + bb * 16;
        float s = row0 * Tb[0 * 4 + k] + row1 * Tb[1 * 4 + k]
                + row2 * Tb[2 * 4 + k] + row3 * Tb[3 * 4 + k];
        tout[bb * 16 + i * 4 + k] = s;
    }
}

extern "C" void kernel_launch(void* const* d_in, const int* in_sizes, int n_in,
                              void* d_out, int out_size) {
    const float* pcd   = (const float*)d_in[0];
    const float* T_mis = (const float*)d_in[1];
    const float* q     = (const float*)d_in[2];
    const float* t     = (const float*)d_in[3];
    float* out = (float*)d_out;

    (void)in_sizes; (void)n_in; (void)out_size;

    pcd_kernel<<<TOTAL_BLOCKS, THREADS>>>((const float4*)pcd, T_mis, q, t,
                                          (float4*)(out + B * 16), out);
}